// round 3
// baseline (speedup 1.0000x reference)
#include <cuda_runtime.h>

// RoIPooling2D (Caffe roi_pool, max): x [B=2, C=256, H=50, W=50] f32,
// rois [N=128, 5] f32 (bidx, x1, y1, x2, y2), out [N, C, 7, 7] f32.
// spatial_scale = 1/16.
//
// Bit-exactness strategy: the JAX reference executes on XLA:GPU, which lowers
// f32 division to div.full.f32 (approximate, <=2ulp). Bin boundaries
// floor(j*bs)/ceil((j+1)*bs) sit exactly on integers (size is integral), so
// the division's rounding direction decides bin extents. We reproduce it with
// inline PTX div.full.f32; all other ops are exact or RN and pinned.

#define POOL_H 7
#define POOL_W 7
#define SPATIAL_SCALE 0.0625f
#define MAX_N 512

__device__ __forceinline__ float div_full(float a, float b) {
    float r;
    asm("div.full.f32 %0, %1, %2;" : "=f"(r) : "f"(a), "f"(b));
    return r;
}

// Per-ROI precomputed bounds (set by setup kernel each launch).
__device__ int   g_bidx[MAX_N];
__device__ short g_hs[MAX_N * POOL_H];
__device__ short g_he[MAX_N * POOL_H];
__device__ short g_ws[MAX_N * POOL_W];
__device__ short g_we[MAX_N * POOL_W];

__global__ void roi_bounds_kernel(const float* __restrict__ rois,
                                  int N, int H, int W) {
    int n = blockIdx.x * blockDim.x + threadIdx.x;
    if (n >= N) return;

    const float* r = rois + n * 5;
    g_bidx[n] = (int)r[0];

    float sx = rintf(__fmul_rn(r[1], SPATIAL_SCALE));
    float sy = rintf(__fmul_rn(r[2], SPATIAL_SCALE));
    float ex = rintf(__fmul_rn(r[3], SPATIAL_SCALE));
    float ey = rintf(__fmul_rn(r[4], SPATIAL_SCALE));

    float roi_w = fmaxf(__fadd_rn(__fsub_rn(ex, sx), 1.0f), 1.0f);
    float roi_h = fmaxf(__fadd_rn(__fsub_rn(ey, sy), 1.0f), 1.0f);
    // XLA:GPU emits div.full.f32 for f32 division — replicate exactly.
    float bin_w = div_full(roi_w, (float)POOL_W);
    float bin_h = div_full(roi_h, (float)POOL_H);

    #pragma unroll
    for (int i = 0; i < POOL_H; ++i) {
        float lo = __fadd_rn(floorf(__fmul_rn((float)i, bin_h)), sy);
        float hi = __fadd_rn(ceilf(__fmul_rn((float)(i + 1), bin_h)), sy);
        lo = fminf(fmaxf(lo, 0.0f), (float)H);
        hi = fminf(fmaxf(hi, 0.0f), (float)H);
        g_hs[n * POOL_H + i] = (short)lo;
        g_he[n * POOL_H + i] = (short)hi;
    }
    #pragma unroll
    for (int j = 0; j < POOL_W; ++j) {
        float lo = __fadd_rn(floorf(__fmul_rn((float)j, bin_w)), sx);
        float hi = __fadd_rn(ceilf(__fmul_rn((float)(j + 1), bin_w)), sx);
        lo = fminf(fmaxf(lo, 0.0f), (float)W);
        hi = fminf(fmaxf(hi, 0.0f), (float)W);
        g_ws[n * POOL_W + j] = (short)lo;
        g_we[n * POOL_W + j] = (short)hi;
    }
}

__global__ void roi_max_pool_kernel(const float* __restrict__ x,
                                    float* __restrict__ out,
                                    int N, int C, int H, int W) {
    int idx = blockIdx.x * blockDim.x + threadIdx.x;
    int total = N * C * POOL_H * POOL_W;
    if (idx >= total) return;

    int pw = idx % POOL_W;
    int ph = (idx / POOL_W) % POOL_H;
    int c  = (idx / (POOL_W * POOL_H)) % C;
    int n  = idx / (POOL_W * POOL_H * C);

    int hstart = g_hs[n * POOL_H + ph];
    int hend   = g_he[n * POOL_H + ph];
    int wstart = g_ws[n * POOL_W + pw];
    int wend   = g_we[n * POOL_W + pw];
    int b      = g_bidx[n];

    bool is_empty = (hend <= hstart) || (wend <= wstart);

    const float* plane = x + ((long)b * C + c) * (long)(H * W);
    float maxval = -3.402823466e38f;
    for (int h = hstart; h < hend; ++h) {
        const float* row = plane + h * W;
        for (int w = wstart; w < wend; ++w) {
            maxval = fmaxf(maxval, __ldg(row + w));
        }
    }
    out[idx] = is_empty ? 0.0f : maxval;
}

extern "C" void kernel_launch(void* const* d_in, const int* in_sizes, int n_in,
                              void* d_out, int out_size) {
    const float* x    = (const float*)d_in[0];   // [2,256,50,50]
    const float* rois = (const float*)d_in[1];   // [128,5]
    float* out = (float*)d_out;                  // [128,256,7,7]

    const int N = in_sizes[1] / 5;               // 128
    const int C = 256, H = 50, W = 50;

    roi_bounds_kernel<<<(N + 127) / 128, 128>>>(rois, N, H, W);

    int total = N * C * POOL_H * POOL_W;
    int threads = 256;
    int blocks = (total + threads - 1) / threads;
    roi_max_pool_kernel<<<blocks, threads>>>(x, out, N, C, H, W);
}

// round 4
// speedup vs baseline: 1.4310x; 1.4310x over previous
#include <cuda_runtime.h>

// RoIPooling2D (Caffe roi_pool, max) — NHWC-transposed gather version.
// x [B=2, C=256, H=50, W=50] f32, rois [N,5] f32, out [N, C, 7, 7] f32.
// spatial_scale = 1/16. Bin bounds replicate XLA:GPU arithmetic exactly:
// f32 division lowered as div.full.f32 (proven bit-exact in Round 3).
//
// Pipeline:
//   1) transpose_in: x NCHW -> g_xt NHWC ([b][h*w][c])  (5.12 MB scratch)
//   2) gather: block = (roi n, channel-half). lane = channel (float4),
//      warp = bin -> zero divergence, coalesced 512B loads. Results staged
//      in smem [c][bin], then written out linearly (coalesced float4 STG).

#define POOL_H 7
#define POOL_W 7
#define NBINS  (POOL_H * POOL_W)       // 49
#define SPATIAL_SCALE 0.0625f
#define C_TOT  256
#define HDIM   50
#define WDIM   50
#define HW     (HDIM * WDIM)           // 2500
#define CH     128                     // channels per gather block
#define GTHREADS 512
#define NEG_FLT_MAX (-3.402823466e38f)

__device__ float g_xt[2 * HW * C_TOT];  // NHWC scratch, 5.12 MB

__device__ __forceinline__ float div_full(float a, float b) {
    float r;
    asm("div.full.f32 %0, %1, %2;" : "=f"(r) : "f"(a), "f"(b));
    return r;
}

__device__ __forceinline__ float4 fmax4(float4 a, float4 b) {
    return make_float4(fmaxf(a.x, b.x), fmaxf(a.y, b.y),
                       fmaxf(a.z, b.z), fmaxf(a.w, b.w));
}

// ---------------- Kernel 1: NCHW -> NHWC transpose ----------------
__global__ void transpose_in_kernel(const float* __restrict__ x) {
    __shared__ float tile[32][33];
    int b  = blockIdx.z;
    int p0 = blockIdx.x * 32;   // spatial (h*W+w)
    int c0 = blockIdx.y * 32;   // channel
    int tx = threadIdx.x;       // 0..31
    int ty = threadIdx.y;       // 0..7

    #pragma unroll
    for (int k = 0; k < 4; ++k) {
        int c = c0 + ty + k * 8;
        int p = p0 + tx;
        if (p < HW)
            tile[ty + k * 8][tx] = x[((size_t)b * C_TOT + c) * HW + p];
    }
    __syncthreads();
    #pragma unroll
    for (int k = 0; k < 4; ++k) {
        int p = p0 + ty + k * 8;
        int c = c0 + tx;
        if (p < HW)
            g_xt[((size_t)b * HW + p) * C_TOT + c] = tile[tx][ty + k * 8];
    }
}

// ---------------- Kernel 2: fused bounds + gather + coalesced write ----------------
__global__ void __launch_bounds__(GTHREADS)
roi_gather_kernel(const float* __restrict__ rois, float* __restrict__ out, int N) {
    __shared__ float s_res[CH * NBINS];   // [c_local][bin], 25 KB
    __shared__ int   s_hs[POOL_H], s_he[POOL_H], s_ws[POOL_W], s_we[POOL_W];
    __shared__ int   s_b;

    int n    = blockIdx.x;
    int half = blockIdx.y;                // 0 or 1 -> channels [half*128, +128)
    int tid  = threadIdx.x;
    int warp = tid >> 5;
    int lane = tid & 31;

    // --- bounds (exact replica of reference arithmetic, incl. div.full) ---
    if (tid < POOL_H + POOL_W + 1) {
        const float* r = rois + n * 5;
        if (tid == POOL_H + POOL_W) {
            s_b = (int)r[0];
        } else {
            bool is_h = (tid < POOL_H);
            int  i    = is_h ? tid : tid - POOL_H;
            float s1  = rintf(__fmul_rn(r[is_h ? 2 : 1], SPATIAL_SCALE));
            float e1  = rintf(__fmul_rn(r[is_h ? 4 : 3], SPATIAL_SCALE));
            float sz  = fmaxf(__fadd_rn(__fsub_rn(e1, s1), 1.0f), 1.0f);
            float bs  = div_full(sz, is_h ? (float)POOL_H : (float)POOL_W);
            float npx = is_h ? (float)HDIM : (float)WDIM;
            float lo = __fadd_rn(floorf(__fmul_rn((float)i, bs)), s1);
            float hi = __fadd_rn(ceilf(__fmul_rn((float)(i + 1), bs)), s1);
            lo = fminf(fmaxf(lo, 0.0f), npx);
            hi = fminf(fmaxf(hi, 0.0f), npx);
            if (is_h) { s_hs[i] = (int)lo; s_he[i] = (int)hi; }
            else      { s_ws[i] = (int)lo; s_we[i] = (int)hi; }
        }
    }
    __syncthreads();

    // --- gather: warp = bin, lane = 4 channels (float4) ---
    int c4 = half * CH + lane * 4;                 // global channel of lane's float4
    const float* xb = g_xt + (size_t)s_b * (HW * C_TOT) + c4;

    for (int bin = warp; bin < NBINS; bin += (GTHREADS / 32)) {
        int ph = bin / POOL_W;
        int pw = bin - ph * POOL_W;
        int hs = s_hs[ph], he = s_he[ph];
        int ws = s_ws[pw], we = s_we[pw];
        bool empty = (he <= hs) || (we <= ws);

        float4 m = make_float4(NEG_FLT_MAX, NEG_FLT_MAX, NEG_FLT_MAX, NEG_FLT_MAX);
        for (int h = hs; h < he; ++h) {
            const float* rowp = xb + (size_t)(h * WDIM) * C_TOT;
            for (int w = ws; w < we; ++w) {
                float4 v = __ldg(reinterpret_cast<const float4*>(rowp + (size_t)w * C_TOT));
                m = fmax4(m, v);
            }
        }
        if (empty) m = make_float4(0.f, 0.f, 0.f, 0.f);

        int cl = lane * 4;                          // local channel
        s_res[(cl + 0) * NBINS + bin] = m.x;
        s_res[(cl + 1) * NBINS + bin] = m.y;
        s_res[(cl + 2) * NBINS + bin] = m.z;
        s_res[(cl + 3) * NBINS + bin] = m.w;
    }
    __syncthreads();

    // --- coalesced linear write: out region [n][half*128 .. +128][:] is contiguous ---
    float* obase = out + (size_t)n * (C_TOT * NBINS) + (size_t)half * (CH * NBINS);
    const float4* src = reinterpret_cast<const float4*>(s_res);
    float4* dst = reinterpret_cast<float4*>(obase);
    const int n4 = (CH * NBINS) / 4;                // 1568
    for (int i = tid; i < n4; i += GTHREADS)
        dst[i] = src[i];
}

extern "C" void kernel_launch(void* const* d_in, const int* in_sizes, int n_in,
                              void* d_out, int out_size) {
    const float* x    = (const float*)d_in[0];   // [B,256,50,50]
    const float* rois = (const float*)d_in[1];   // [N,5]
    float* out = (float*)d_out;                  // [N,256,7,7]

    const int N = in_sizes[1] / 5;
    const int B = in_sizes[0] / (C_TOT * HW);

    dim3 tgrid((HW + 31) / 32, C_TOT / 32, B);
    dim3 tblock(32, 8);
    transpose_in_kernel<<<tgrid, tblock>>>(x);

    dim3 ggrid(N, C_TOT / CH);                   // (128, 2)
    roi_gather_kernel<<<ggrid, GTHREADS>>>(rois, out, N);
}